// round 10
// baseline (speedup 1.0000x reference)
#include <cuda_runtime.h>
#include <math.h>
#include <stdint.h>

#define B_   32
#define M_   196
#define D_   512
#define N_   51
#define C_   1000
#define KTOP 50

#define LOCPAD 225   // odd stride -> conflict-free transposed stores
#define DC     64    // d-chunk staged in smem

// ---------------- device-global scratch (allocation-free) ----------------
__device__ __align__(16) float g_txtn[(size_t)N_ * C_ * D_]; // normalized text [n][c][d]
__device__ __align__(16) float g_mean[C_ * D_];              // l2norm(mean_n txt) [c][d]
__device__ __align__(16) float g_v[C_ * N_];                 // softmax weights [c][n]
__device__ __align__(16) float g_imgn[B_ * D_];              // normalized image [b][d]
__device__ __align__(16) float g_locn[(size_t)B_ * M_ * D_]; // normalized local [b][m][d]
__device__ __align__(16) float g_ew[B_ * M_];                // exp(5*w_raw) [b][m]
__device__ __align__(16) float g_base[B_ * C_];              // base logits [b][c]

// ---------------- helpers ----------------
__device__ __forceinline__ float warp_sum(float v) {
#pragma unroll
    for (int o = 16; o; o >>= 1) v += __shfl_xor_sync(0xffffffffu, v, o);
    return v;
}
__device__ __forceinline__ float dot4(float4 a, float4 b) {
    return a.x * b.x + a.y * b.y + a.z * b.z + a.w * b.w;
}
// monotone float -> uint mapping (order-preserving)
__device__ __forceinline__ unsigned ford(float x) {
    unsigned i = __float_as_uint(x);
    return (i & 0x80000000u) ? ~i : (i | 0x80000000u);
}

// ---------------- K1: l2-normalize all text rows (51*1000 rows of 512) ----------------
__global__ void k_txt_norm(const float* __restrict__ txt) {
    int w = (blockIdx.x * blockDim.x + threadIdx.x) >> 5;
    int lane = threadIdx.x & 31;
    if (w >= N_ * C_) return;
    const float4* src = (const float4*)(txt + (size_t)w * D_);
    float4* dst = (float4*)(g_txtn + (size_t)w * D_);
    float4 x0 = src[lane], x1 = src[lane + 32], x2 = src[lane + 64], x3 = src[lane + 96];
    float ss = dot4(x0, x0) + dot4(x1, x1) + dot4(x2, x2) + dot4(x3, x3);
    ss = warp_sum(ss);
    float inv = rsqrtf(ss);
    dst[lane]      = make_float4(x0.x * inv, x0.y * inv, x0.z * inv, x0.w * inv);
    dst[lane + 32] = make_float4(x1.x * inv, x1.y * inv, x1.z * inv, x1.w * inv);
    dst[lane + 64] = make_float4(x2.x * inv, x2.y * inv, x2.z * inv, x2.w * inv);
    dst[lane + 96] = make_float4(x3.x * inv, x3.y * inv, x3.z * inv, x3.w * inv);
}

// ---------------- K2: image normalization (32 rows, 1 block of 32 warps) ----------------
__global__ void k_img(const float* __restrict__ img) {
    int w = threadIdx.x >> 5;
    int lane = threadIdx.x & 31;
    const float4* src = (const float4*)(img + (size_t)w * D_);
    float4* dst = (float4*)(g_imgn + (size_t)w * D_);
    float4 x0 = src[lane], x1 = src[lane + 32], x2 = src[lane + 64], x3 = src[lane + 96];
    float ss = dot4(x0, x0) + dot4(x1, x1) + dot4(x2, x2) + dot4(x3, x3);
    ss = warp_sum(ss);
    float inv = rsqrtf(ss);
    dst[lane]      = make_float4(x0.x * inv, x0.y * inv, x0.z * inv, x0.w * inv);
    dst[lane + 32] = make_float4(x1.x * inv, x1.y * inv, x1.z * inv, x1.w * inv);
    dst[lane + 64] = make_float4(x2.x * inv, x2.y * inv, x2.z * inv, x2.w * inv);
    dst[lane + 96] = make_float4(x3.x * inv, x3.y * inv, x3.z * inv, x3.w * inv);
}

// ---------------- K3: mean over n then l2norm (the /51 cancels under l2norm) ----------------
__global__ void k_mean() {
    __shared__ float red[128];
    int c = blockIdx.x, tid = threadIdx.x;   // 128 threads, each owns 4 dims
    float4 a = make_float4(0.f, 0.f, 0.f, 0.f);
    for (int n = 0; n < N_; ++n) {
        float4 t = *(const float4*)(g_txtn + ((size_t)n * C_ + c) * D_ + 4 * tid);
        a.x += t.x; a.y += t.y; a.z += t.z; a.w += t.w;
    }
    red[tid] = dot4(a, a);
    __syncthreads();
    for (int s = 64; s > 0; s >>= 1) {
        if (tid < s) red[tid] += red[tid + s];
        __syncthreads();
    }
    float inv = rsqrtf(red[0]);
    *(float4*)(g_mean + (size_t)c * D_ + 4 * tid) =
        make_float4(a.x * inv, a.y * inv, a.z * inv, a.w * inv);
}

// ---------------- K4: v[c][n] = softmax_n( 5 * mean_txt[c] . txt[n][c] ) ----------------
__global__ void k_v() {
    __shared__ __align__(16) float mean_s[D_];
    __shared__ float dots[56];
    int c = blockIdx.x, tid = threadIdx.x;   // 256 threads
    int w = tid >> 5, lane = tid & 31;
    if (tid < 128)
        *(float4*)(mean_s + 4 * tid) = *(const float4*)(g_mean + (size_t)c * D_ + 4 * tid);
    __syncthreads();
#pragma unroll
    for (int j = 0; j < 7; ++j) {
        int n = w + 8 * j;
        if (n < N_) {
            const float4* t = (const float4*)(g_txtn + ((size_t)n * C_ + c) * D_);
            const float4* m = (const float4*)mean_s;
            float d = 0.f;
#pragma unroll
            for (int q = 0; q < 4; ++q) d += dot4(t[lane + 32 * q], m[lane + 32 * q]);
            d = warp_sum(d);
            if (lane == 0) dots[n] = d;
        }
    }
    __syncthreads();
    if (tid < 32) {
        float e0 = (tid < N_) ? expf(5.f * dots[tid]) : 0.f;
        float e1 = (tid + 32 < N_) ? expf(5.f * dots[tid + 32]) : 0.f;
        float s = warp_sum(e0 + e1);
        if (tid < N_) g_v[c * N_ + tid] = e0 / s;
        if (tid + 32 < N_) g_v[c * N_ + tid + 32] = e1 / s;
    }
}

// ---------------- K5: normalize loc rows + ew = exp(5 * img_n . loc_n) ----------------
__global__ void k_loc(const float* __restrict__ loc) {
    int w = (blockIdx.x * blockDim.x + threadIdx.x) >> 5;
    int lane = threadIdx.x & 31;
    if (w >= B_ * M_) return;
    int b = w / M_;
    const float4* src = (const float4*)(loc + (size_t)w * D_);
    const float4* iv  = (const float4*)(g_imgn + (size_t)b * D_);
    float4* dst = (float4*)(g_locn + (size_t)w * D_);
    float4 x0 = src[lane], x1 = src[lane + 32], x2 = src[lane + 64], x3 = src[lane + 96];
    float4 y0 = iv[lane],  y1 = iv[lane + 32],  y2 = iv[lane + 64],  y3 = iv[lane + 96];
    float ss = dot4(x0, x0) + dot4(x1, x1) + dot4(x2, x2) + dot4(x3, x3);
    float dt = dot4(x0, y0) + dot4(x1, y1) + dot4(x2, y2) + dot4(x3, y3);
    ss = warp_sum(ss);
    dt = warp_sum(dt);
    float inv = rsqrtf(ss);
    dst[lane]      = make_float4(x0.x * inv, x0.y * inv, x0.z * inv, x0.w * inv);
    dst[lane + 32] = make_float4(x1.x * inv, x1.y * inv, x1.z * inv, x1.w * inv);
    dst[lane + 64] = make_float4(x2.x * inv, x2.y * inv, x2.z * inv, x2.w * inv);
    dst[lane + 96] = make_float4(x3.x * inv, x3.y * inv, x3.z * inv, x3.w * inv);
    if (lane == 0) g_ew[w] = expf(5.f * dt * inv);
}

// ---------------- K6: base_logits[b][c] = img_n[b] . mean_txt[c] ----------------
__global__ void k_base() {
    int c = blockIdx.x;
    int w = threadIdx.x >> 5, lane = threadIdx.x & 31;   // 256 threads
#pragma unroll
    for (int j = 0; j < 4; ++j) {
        int b = w + 8 * j;
        const float4* iv = (const float4*)(g_imgn + (size_t)b * D_);
        const float4* mv = (const float4*)(g_mean + (size_t)c * D_);
        float d = 0.f;
#pragma unroll
        for (int q = 0; q < 4; ++q) d += dot4(iv[lane + 32 * q], mv[lane + 32 * q]);
        d = warp_sum(d);
        if (lane == 0) g_base[b * C_ + c] = d;
    }
}

// ---------------- K7: fused sim-GEMM + exact top-50 radix select + weighted sum ----------
// grid (b=32, c=1000), 256 threads. warp w owns rows n = w + 8i; lane owns m = lane + 32j.
// S stays in registers: acc[i][j]. Selection is warp-local on the producing warp.
#define SMEM_MAIN ((56 * 512 + DC * LOCPAD + 224 + 51 + 8) * 4)

extern "C" __global__ void __launch_bounds__(256, 1)
k_main(const float* __restrict__ ls_ptr, float* __restrict__ out) {
    extern __shared__ float sm[];
    float* txt_s = sm;                     // [56][512] rows >= 51 zero
    float* loc_s = txt_s + 56 * 512;       // [DC][LOCPAD] cols >= 196 zero
    float* ew_s  = loc_s + DC * LOCPAD;    // [224]
    float* v_s   = ew_s + 224;             // [51]
    float* red_s = v_s + 51;               // [8]

    int b = blockIdx.x, c = blockIdx.y;
    int tid = threadIdx.x;
    int lane = tid & 31, w = tid >> 5;

    // stage txt[:, c, :] with zero-padded n rows 51..55
    for (int idx = tid; idx < 56 * 128; idx += 256) {
        int n = idx >> 7, q = idx & 127;
        float4 t = make_float4(0.f, 0.f, 0.f, 0.f);
        if (n < N_) t = *(const float4*)(g_txtn + ((size_t)n * C_ + c) * D_ + 4 * q);
        *(float4*)(txt_s + n * 512 + 4 * q) = t;
    }
    // zero loc pad columns (never rewritten)
    for (int idx = tid; idx < DC * (LOCPAD - 196); idx += 256) {
        int d = idx / (LOCPAD - 196), m = 196 + idx % (LOCPAD - 196);
        loc_s[d * LOCPAD + m] = 0.f;
    }
    if (tid < 196) ew_s[tid] = g_ew[b * M_ + tid];
    else if (tid < 224) ew_s[tid] = 0.f;
    if (tid < N_) v_s[tid] = g_v[c * N_ + tid];

    float acc[7][7];
#pragma unroll
    for (int i = 0; i < 7; ++i)
#pragma unroll
        for (int j = 0; j < 7; ++j) acc[i][j] = 0.f;

    for (int d0 = 0; d0 < D_; d0 += DC) {
        __syncthreads();
        // transpose-load loc chunk: warp over m, lanes over d (coalesced global,
        // odd-stride smem writes -> conflict-free)
        for (int m = w; m < 196; m += 8) {
            const float* src = g_locn + ((size_t)(b * M_ + m)) * D_ + d0;
            loc_s[lane * LOCPAD + m]        = src[lane];
            loc_s[(lane + 32) * LOCPAD + m] = src[lane + 32];
        }
        __syncthreads();
#pragma unroll 2
        for (int dd = 0; dd < DC; dd += 4) {
            float4 t[7];
#pragma unroll
            for (int i = 0; i < 7; ++i)
                t[i] = *(const float4*)(txt_s + (w + 8 * i) * 512 + d0 + dd);  // broadcast
#pragma unroll
            for (int q = 0; q < 4; ++q) {
                float l[7];
#pragma unroll
                for (int j = 0; j < 7; ++j)
                    l[j] = loc_s[(dd + q) * LOCPAD + lane + 32 * j];           // conflict-free
#pragma unroll
                for (int i = 0; i < 7; ++i) {
                    float tv = (q == 0) ? t[i].x : (q == 1) ? t[i].y : (q == 2) ? t[i].z : t[i].w;
#pragma unroll
                    for (int j = 0; j < 7; ++j) acc[i][j] = fmaf(tv, l[j], acc[i][j]);
                }
            }
        }
    }

    // -------- per-row exact top-50 + softmax-weighted sum (all warp-local) --------
    float bias = 0.f;
#pragma unroll 1
    for (int i = 0; i < 7; ++i) {
        int n = w + 8 * i;
        if (n >= N_) break;                       // warp-uniform
        unsigned keys[7];
#pragma unroll
        for (int j = 0; j < 7; ++j) {
            int m = lane + 32 * j;
            keys[j] = (m < 196) ? ford(acc[i][j]) : 0u;   // mask pad m
        }
        // radix threshold: largest T with count(key >= T) >= K  => T == K-th largest key
        unsigned T = 0u;
#pragma unroll 1
        for (int bit = 31; bit >= 0; --bit) {
            unsigned cand = T | (1u << bit);
            int cnt = 0;
#pragma unroll
            for (int j = 0; j < 7; ++j) cnt += (keys[j] >= cand);
            cnt = __reduce_add_sync(0xffffffffu, cnt);
            if (cnt >= KTOP) T = cand;
        }
        float se = 0.f, sw = 0.f;
        int cgt = 0;
#pragma unroll
        for (int j = 0; j < 7; ++j) {
            if (keys[j] > T) {
                float e = ew_s[lane + 32 * j];
                se += acc[i][j] * e; sw += e; cgt++;
            }
        }
        int rem = KTOP - __reduce_add_sync(0xffffffffu, cgt);   // >=1 by construction
        // ties at T: take lowest m first (JAX stable tie-break); m order = (j, lane)
#pragma unroll 1
        for (int j = 0; j < 7; ++j) {
            if (rem <= 0) break;                                // warp-uniform
            unsigned eq = __ballot_sync(0xffffffffu, keys[j] == T);
            int below = __popc(eq & ((1u << lane) - 1u));
            if ((keys[j] == T) && below < rem) {
                float e = ew_s[lane + 32 * j];
                se += acc[i][j] * e; sw += e;
            }
            int take = __popc(eq);
            rem -= (take < rem ? take : rem);
        }
        se = warp_sum(se);
        sw = warp_sum(sw);
        bias += v_s[n] * se / sw;   // == sum_k sim_k * softmax(5*w_raw)_k * v[c][n]
    }
    if (lane == 0) red_s[w] = bias;
    __syncthreads();
    if (tid == 0) {
        float t = 0.f;
#pragma unroll
        for (int k = 0; k < 8; ++k) t += red_s[k];
        out[b * C_ + c] = expf(ls_ptr[0]) * (g_base[b * C_ + c] + t);
    }
}

// ---------------- launch ----------------
extern "C" void kernel_launch(void* const* d_in, const int* in_sizes, int n_in,
                              void* d_out, int out_size) {
    (void)in_sizes; (void)n_in; (void)out_size;
    const float* img = (const float*)d_in[0];
    const float* loc = (const float*)d_in[1];
    const float* txt = (const float*)d_in[2];
    const float* ls  = (const float*)d_in[3];
    float* out = (float*)d_out;

    k_txt_norm<<<(N_ * C_ + 7) / 8, 256>>>(txt);
    k_img<<<1, 1024>>>(img);
    k_mean<<<C_, 128>>>();
    k_v<<<C_, 256>>>();
    k_loc<<<(B_ * M_ + 7) / 8, 256>>>(loc);
    k_base<<<C_, 256>>>();

    cudaFuncSetAttribute(k_main, cudaFuncAttributeMaxDynamicSharedMemorySize, SMEM_MAIN);
    dim3 grid(B_, C_);   // b fastest -> 32 adjacent blocks share one txt slice in L2
    k_main<<<grid, 256, SMEM_MAIN>>>(ls, out);
}

// round 13
// speedup vs baseline: 1.0017x; 1.0017x over previous
#include <cuda_runtime.h>
#include <math.h>
#include <stdint.h>

#define B_   32
#define M_   196
#define D_   512
#define N_   51
#define C_   1000
#define KTOP 50

#define LOCPAD 225   // odd stride -> conflict-free transposed stores
#define DC     64    // d-chunk staged in smem

// ---------------- device-global scratch (allocation-free) ----------------
__device__ __align__(16) float g_txtn[(size_t)N_ * C_ * D_]; // normalized text [n][c][d]
__device__ __align__(16) float g_mean[C_ * D_];              // l2norm(mean_n txt) [c][d]
__device__ __align__(16) float g_v[C_ * N_];                 // softmax weights [c][n]
__device__ __align__(16) float g_imgn[B_ * D_];              // normalized image [b][d]
__device__ __align__(16) float g_locn[(size_t)B_ * M_ * D_]; // normalized local [b][m][d]
__device__ __align__(16) float g_ew[B_ * M_];                // exp(5*w_raw) [b][m]
__device__ __align__(16) float g_base[B_ * C_];              // base logits [b][c]

// ---------------- helpers ----------------
__device__ __forceinline__ float warp_sum(float v) {
#pragma unroll
    for (int o = 16; o; o >>= 1) v += __shfl_xor_sync(0xffffffffu, v, o);
    return v;
}
__device__ __forceinline__ float dot4(float4 a, float4 b) {
    return a.x * b.x + a.y * b.y + a.z * b.z + a.w * b.w;
}
// monotone float -> uint mapping (order-preserving)
__device__ __forceinline__ unsigned ford(float x) {
    unsigned i = __float_as_uint(x);
    return (i & 0x80000000u) ? ~i : (i | 0x80000000u);
}

// ---------------- K1: l2-normalize all text rows (51*1000 rows of 512) ----------------
__global__ void k_txt_norm(const float* __restrict__ txt) {
    int w = (blockIdx.x * blockDim.x + threadIdx.x) >> 5;
    int lane = threadIdx.x & 31;
    if (w >= N_ * C_) return;
    const float4* src = (const float4*)(txt + (size_t)w * D_);
    float4* dst = (float4*)(g_txtn + (size_t)w * D_);
    float4 x0 = src[lane], x1 = src[lane + 32], x2 = src[lane + 64], x3 = src[lane + 96];
    float ss = dot4(x0, x0) + dot4(x1, x1) + dot4(x2, x2) + dot4(x3, x3);
    ss = warp_sum(ss);
    float inv = rsqrtf(ss);
    dst[lane]      = make_float4(x0.x * inv, x0.y * inv, x0.z * inv, x0.w * inv);
    dst[lane + 32] = make_float4(x1.x * inv, x1.y * inv, x1.z * inv, x1.w * inv);
    dst[lane + 64] = make_float4(x2.x * inv, x2.y * inv, x2.z * inv, x2.w * inv);
    dst[lane + 96] = make_float4(x3.x * inv, x3.y * inv, x3.z * inv, x3.w * inv);
}

// ---------------- K2: image normalization (32 rows, 1 block of 32 warps) ----------------
__global__ void k_img(const float* __restrict__ img) {
    int w = threadIdx.x >> 5;
    int lane = threadIdx.x & 31;
    const float4* src = (const float4*)(img + (size_t)w * D_);
    float4* dst = (float4*)(g_imgn + (size_t)w * D_);
    float4 x0 = src[lane], x1 = src[lane + 32], x2 = src[lane + 64], x3 = src[lane + 96];
    float ss = dot4(x0, x0) + dot4(x1, x1) + dot4(x2, x2) + dot4(x3, x3);
    ss = warp_sum(ss);
    float inv = rsqrtf(ss);
    dst[lane]      = make_float4(x0.x * inv, x0.y * inv, x0.z * inv, x0.w * inv);
    dst[lane + 32] = make_float4(x1.x * inv, x1.y * inv, x1.z * inv, x1.w * inv);
    dst[lane + 64] = make_float4(x2.x * inv, x2.y * inv, x2.z * inv, x2.w * inv);
    dst[lane + 96] = make_float4(x3.x * inv, x3.y * inv, x3.z * inv, x3.w * inv);
}

// ---------------- K3: mean over n then l2norm (the /51 cancels under l2norm) ----------------
__global__ void k_mean() {
    __shared__ float red[128];
    int c = blockIdx.x, tid = threadIdx.x;   // 128 threads, each owns 4 dims
    float4 a = make_float4(0.f, 0.f, 0.f, 0.f);
    for (int n = 0; n < N_; ++n) {
        float4 t = *(const float4*)(g_txtn + ((size_t)n * C_ + c) * D_ + 4 * tid);
        a.x += t.x; a.y += t.y; a.z += t.z; a.w += t.w;
    }
    red[tid] = dot4(a, a);
    __syncthreads();
    for (int s = 64; s > 0; s >>= 1) {
        if (tid < s) red[tid] += red[tid + s];
        __syncthreads();
    }
    float inv = rsqrtf(red[0]);
    *(float4*)(g_mean + (size_t)c * D_ + 4 * tid) =
        make_float4(a.x * inv, a.y * inv, a.z * inv, a.w * inv);
}

// ---------------- K4: v[c][n] = softmax_n( 5 * mean_txt[c] . txt[n][c] ) ----------------
__global__ void k_v() {
    __shared__ __align__(16) float mean_s[D_];
    __shared__ float dots[56];
    int c = blockIdx.x, tid = threadIdx.x;   // 256 threads
    int w = tid >> 5, lane = tid & 31;
    if (tid < 128)
        *(float4*)(mean_s + 4 * tid) = *(const float4*)(g_mean + (size_t)c * D_ + 4 * tid);
    __syncthreads();
#pragma unroll
    for (int j = 0; j < 7; ++j) {
        int n = w + 8 * j;
        if (n < N_) {
            const float4* t = (const float4*)(g_txtn + ((size_t)n * C_ + c) * D_);
            const float4* m = (const float4*)mean_s;
            float d = 0.f;
#pragma unroll
            for (int q = 0; q < 4; ++q) d += dot4(t[lane + 32 * q], m[lane + 32 * q]);
            d = warp_sum(d);
            if (lane == 0) dots[n] = d;
        }
    }
    __syncthreads();
    if (tid < 32) {
        float e0 = (tid < N_) ? expf(5.f * dots[tid]) : 0.f;
        float e1 = (tid + 32 < N_) ? expf(5.f * dots[tid + 32]) : 0.f;
        float s = warp_sum(e0 + e1);
        if (tid < N_) g_v[c * N_ + tid] = e0 / s;
        if (tid + 32 < N_) g_v[c * N_ + tid + 32] = e1 / s;
    }
}

// ---------------- K5: normalize loc rows + ew = exp(5 * img_n . loc_n) ----------------
__global__ void k_loc(const float* __restrict__ loc) {
    int w = (blockIdx.x * blockDim.x + threadIdx.x) >> 5;
    int lane = threadIdx.x & 31;
    if (w >= B_ * M_) return;
    int b = w / M_;
    const float4* src = (const float4*)(loc + (size_t)w * D_);
    const float4* iv  = (const float4*)(g_imgn + (size_t)b * D_);
    float4* dst = (float4*)(g_locn + (size_t)w * D_);
    float4 x0 = src[lane], x1 = src[lane + 32], x2 = src[lane + 64], x3 = src[lane + 96];
    float4 y0 = iv[lane],  y1 = iv[lane + 32],  y2 = iv[lane + 64],  y3 = iv[lane + 96];
    float ss = dot4(x0, x0) + dot4(x1, x1) + dot4(x2, x2) + dot4(x3, x3);
    float dt = dot4(x0, y0) + dot4(x1, y1) + dot4(x2, y2) + dot4(x3, y3);
    ss = warp_sum(ss);
    dt = warp_sum(dt);
    float inv = rsqrtf(ss);
    dst[lane]      = make_float4(x0.x * inv, x0.y * inv, x0.z * inv, x0.w * inv);
    dst[lane + 32] = make_float4(x1.x * inv, x1.y * inv, x1.z * inv, x1.w * inv);
    dst[lane + 64] = make_float4(x2.x * inv, x2.y * inv, x2.z * inv, x2.w * inv);
    dst[lane + 96] = make_float4(x3.x * inv, x3.y * inv, x3.z * inv, x3.w * inv);
    if (lane == 0) g_ew[w] = expf(5.f * dt * inv);
}

// ---------------- K6: base_logits[b][c] = img_n[b] . mean_txt[c] ----------------
__global__ void k_base() {
    int c = blockIdx.x;
    int w = threadIdx.x >> 5, lane = threadIdx.x & 31;   // 256 threads
#pragma unroll
    for (int j = 0; j < 4; ++j) {
        int b = w + 8 * j;
        const float4* iv = (const float4*)(g_imgn + (size_t)b * D_);
        const float4* mv = (const float4*)(g_mean + (size_t)c * D_);
        float d = 0.f;
#pragma unroll
        for (int q = 0; q < 4; ++q) d += dot4(iv[lane + 32 * q], mv[lane + 32 * q]);
        d = warp_sum(d);
        if (lane == 0) g_base[b * C_ + c] = d;
    }
}

// ---------------- K7: fused sim-GEMM + exact top-50 radix select + weighted sum ----------
// grid (b=32, c=1000), 256 threads. warp w owns rows n = w + 8i; lane owns m = lane + 32j.
// S stays in registers: acc[i][j]. Selection is warp-local on the producing warp.
#define SMEM_MAIN ((56 * 512 + DC * LOCPAD + 224 + 51 + 8) * 4)

extern "C" __global__ void __launch_bounds__(256, 1)
k_main(const float* __restrict__ ls_ptr, float* __restrict__ out) {
    extern __shared__ float sm[];
    float* txt_s = sm;                     // [56][512] rows >= 51 zero
    float* loc_s = txt_s + 56 * 512;       // [DC][LOCPAD] cols >= 196 zero
    float* ew_s  = loc_s + DC * LOCPAD;    // [224]
    float* v_s   = ew_s + 224;             // [51]
    float* red_s = v_s + 51;               // [8]

    int b = blockIdx.x, c = blockIdx.y;
    int tid = threadIdx.x;
    int lane = tid & 31, w = tid >> 5;

    // stage txt[:, c, :] with zero-padded n rows 51..55
    for (int idx = tid; idx < 56 * 128; idx += 256) {
        int n = idx >> 7, q = idx & 127;
        float4 t = make_float4(0.f, 0.f, 0.f, 0.f);
        if (n < N_) t = *(const float4*)(g_txtn + ((size_t)n * C_ + c) * D_ + 4 * q);
        *(float4*)(txt_s + n * 512 + 4 * q) = t;
    }
    // zero loc pad columns (never rewritten)
    for (int idx = tid; idx < DC * (LOCPAD - 196); idx += 256) {
        int d = idx / (LOCPAD - 196), m = 196 + idx % (LOCPAD - 196);
        loc_s[d * LOCPAD + m] = 0.f;
    }
    if (tid < 196) ew_s[tid] = g_ew[b * M_ + tid];
    else if (tid < 224) ew_s[tid] = 0.f;
    if (tid < N_) v_s[tid] = g_v[c * N_ + tid];

    float acc[7][7];
#pragma unroll
    for (int i = 0; i < 7; ++i)
#pragma unroll
        for (int j = 0; j < 7; ++j) acc[i][j] = 0.f;

    for (int d0 = 0; d0 < D_; d0 += DC) {
        __syncthreads();
        // transpose-load loc chunk: warp over m, lanes over d (coalesced global,
        // odd-stride smem writes -> conflict-free)
        for (int m = w; m < 196; m += 8) {
            const float* src = g_locn + ((size_t)(b * M_ + m)) * D_ + d0;
            loc_s[lane * LOCPAD + m]        = src[lane];
            loc_s[(lane + 32) * LOCPAD + m] = src[lane + 32];
        }
        __syncthreads();
#pragma unroll 2
        for (int dd = 0; dd < DC; dd += 4) {
            float4 t[7];
#pragma unroll
            for (int i = 0; i < 7; ++i)
                t[i] = *(const float4*)(txt_s + (w + 8 * i) * 512 + d0 + dd);  // broadcast
#pragma unroll
            for (int q = 0; q < 4; ++q) {
                float l[7];
#pragma unroll
                for (int j = 0; j < 7; ++j)
                    l[j] = loc_s[(dd + q) * LOCPAD + lane + 32 * j];           // conflict-free
#pragma unroll
                for (int i = 0; i < 7; ++i) {
                    float tv = (q == 0) ? t[i].x : (q == 1) ? t[i].y : (q == 2) ? t[i].z : t[i].w;
#pragma unroll
                    for (int j = 0; j < 7; ++j) acc[i][j] = fmaf(tv, l[j], acc[i][j]);
                }
            }
        }
    }

    // -------- per-row exact top-50 + softmax-weighted sum (all warp-local) --------
    float bias = 0.f;
#pragma unroll 1
    for (int i = 0; i < 7; ++i) {
        int n = w + 8 * i;
        if (n >= N_) break;                       // warp-uniform
        unsigned keys[7];
#pragma unroll
        for (int j = 0; j < 7; ++j) {
            int m = lane + 32 * j;
            keys[j] = (m < 196) ? ford(acc[i][j]) : 0u;   // mask pad m
        }
        // radix threshold: largest T with count(key >= T) >= K  => T == K-th largest key
        unsigned T = 0u;
#pragma unroll 1
        for (int bit = 31; bit >= 0; --bit) {
            unsigned cand = T | (1u << bit);
            int cnt = 0;
#pragma unroll
            for (int j = 0; j < 7; ++j) cnt += (keys[j] >= cand);
            cnt = __reduce_add_sync(0xffffffffu, cnt);
            if (cnt >= KTOP) T = cand;
        }
        float se = 0.f, sw = 0.f;
        int cgt = 0;
#pragma unroll
        for (int j = 0; j < 7; ++j) {
            if (keys[j] > T) {
                float e = ew_s[lane + 32 * j];
                se += acc[i][j] * e; sw += e; cgt++;
            }
        }
        int rem = KTOP - __reduce_add_sync(0xffffffffu, cgt);   // >=1 by construction
        // ties at T: take lowest m first (JAX stable tie-break); m order = (j, lane)
#pragma unroll 1
        for (int j = 0; j < 7; ++j) {
            if (rem <= 0) break;                                // warp-uniform
            unsigned eq = __ballot_sync(0xffffffffu, keys[j] == T);
            int below = __popc(eq & ((1u << lane) - 1u));
            if ((keys[j] == T) && below < rem) {
                float e = ew_s[lane + 32 * j];
                se += acc[i][j] * e; sw += e;
            }
            int take = __popc(eq);
            rem -= (take < rem ? take : rem);
        }
        se = warp_sum(se);
        sw = warp_sum(sw);
        bias += v_s[n] * se / sw;   // == sum_k sim_k * softmax(5*w_raw)_k * v[c][n]
    }
    if (lane == 0) red_s[w] = bias;
    __syncthreads();
    if (tid == 0) {
        float t = 0.f;
#pragma unroll
        for (int k = 0; k < 8; ++k) t += red_s[k];
        out[b * C_ + c] = expf(ls_ptr[0]) * (g_base[b * C_ + c] + t);
    }
}

// ---------------- launch ----------------
extern "C" void kernel_launch(void* const* d_in, const int* in_sizes, int n_in,
                              void* d_out, int out_size) {
    (void)in_sizes; (void)n_in; (void)out_size;
    const float* img = (const float*)d_in[0];
    const float* loc = (const float*)d_in[1];
    const float* txt = (const float*)d_in[2];
    const float* ls  = (const float*)d_in[3];
    float* out = (float*)d_out;

    k_txt_norm<<<(N_ * C_ + 7) / 8, 256>>>(txt);
    k_img<<<1, 1024>>>(img);
    k_mean<<<C_, 128>>>();
    k_v<<<C_, 256>>>();
    k_loc<<<(B_ * M_ + 7) / 8, 256>>>(loc);
    k_base<<<C_, 256>>>();

    cudaFuncSetAttribute(k_main, cudaFuncAttributeMaxDynamicSharedMemorySize, SMEM_MAIN);
    dim3 grid(B_, C_);   // b fastest -> 32 adjacent blocks share one txt slice in L2
    k_main<<<grid, 256, SMEM_MAIN>>>(ls, out);
}